// round 3
// baseline (speedup 1.0000x reference)
#include <cuda_runtime.h>
#include <cstdint>

#define NN 50000
#define NE 1600000
#define DIN 256
#define DH 128
#define DO 40

#define SCAN_BLK 512
#define SCAN_NB ((NN + SCAN_BLK - 1) / SCAN_BLK)   // 98

// -------- scratch (static device globals; no allocation allowed) --------
static __device__ __align__(16) float g_h1[(size_t)NN * DH];   // x @ W1
static __device__ __align__(16) float g_a1[(size_t)NN * DH];   // aggregated layer1
static __device__ __align__(16) float g_h2[(size_t)NN * DO];   // relu(a1+b1) @ W2
static __device__ int   g_deg[NN];
static __device__ float g_dinv[NN];
static __device__ int   g_off[NN];     // exclusive CSR row offsets (by dst)
static __device__ int   g_pos[NN];     // running fill cursor
static __device__ int   g_inc[SCAN_NB * SCAN_BLK];
static __device__ int   g_bsum[SCAN_NB];
static __device__ int   g_boff[SCAN_NB];
static __device__ int   g_cs[NE];      // CSR: source node per slot
static __device__ float g_cc[NE];      // CSR: coef per slot
static __device__ int   g_is64;        // edge_index dtype flag (device-detected)

// -------- edge index accessors (dtype-agnostic) --------
__device__ __forceinline__ int e_src(const void* ei, int t) {
    return g_is64 ? (int)((const long long*)ei)[t] : ((const int*)ei)[t];
}
__device__ __forceinline__ int e_dst(const void* ei, int t) {
    return g_is64 ? (int)((const long long*)ei)[NE + t] : ((const int*)ei)[NE + t];
}

// -------- dtype detection: odd 32-bit words all zero <=> int64 --------
__global__ void k_detect(const int* __restrict__ ei32) {
    int t = threadIdx.x;
    if (t == 0) g_is64 = 1;
    __syncthreads();
    int any = 0;
    for (int i = t; i < 2048; i += blockDim.x) any |= ei32[2 * i + 1];
    if (any) g_is64 = 0;
}

// -------- degree / normalization --------
__global__ void k_zero_deg() {
    int t = blockIdx.x * blockDim.x + threadIdx.x;
    if (t < NN) g_deg[t] = 0;
}

__global__ void k_deg(const void* __restrict__ ei) {
    int t = blockIdx.x * blockDim.x + threadIdx.x;
    if (t < NE) {
        int d = e_dst(ei, t);
        if ((unsigned)d < NN) atomicAdd(&g_deg[d], 1);
    }
}

__global__ void k_dinv() {
    int t = blockIdx.x * blockDim.x + threadIdx.x;
    if (t < NN) g_dinv[t] = rsqrtf((float)(g_deg[t] + 1));  // +1 self-loop
}

// -------- two-level exclusive scan of g_deg -> g_off --------
__global__ void k_scan_block() {
    __shared__ int sh[SCAN_BLK];
    int t = threadIdx.x;
    int i = blockIdx.x * SCAN_BLK + t;
    int v = (i < NN) ? g_deg[i] : 0;
    sh[t] = v;
    __syncthreads();
#pragma unroll
    for (int o = 1; o < SCAN_BLK; o <<= 1) {
        int x = (t >= o) ? sh[t - o] : 0;
        __syncthreads();
        sh[t] += x;
        __syncthreads();
    }
    g_inc[i] = sh[t];
    if (t == SCAN_BLK - 1) g_bsum[blockIdx.x] = sh[t];
}

__global__ void k_scan_top() {
    __shared__ int sh[128];
    int t = threadIdx.x;
    int v = (t < SCAN_NB) ? g_bsum[t] : 0;
    sh[t] = v;
    __syncthreads();
#pragma unroll
    for (int o = 1; o < 128; o <<= 1) {
        int x = (t >= o) ? sh[t - o] : 0;
        __syncthreads();
        sh[t] += x;
        __syncthreads();
    }
    if (t < SCAN_NB) g_boff[t] = sh[t] - v;  // exclusive
}

__global__ void k_scan_fix() {
    int t = blockIdx.x * blockDim.x + threadIdx.x;
    if (t < NN) {
        int off = g_inc[t] - g_deg[t] + g_boff[t / SCAN_BLK];  // exclusive
        g_off[t] = off;
        g_pos[t] = off;
    }
}

// -------- CSR fill: bucket edges by dst, store (src, coef) --------
__global__ void k_scatter(const void* __restrict__ ei) {
    int t = blockIdx.x * blockDim.x + threadIdx.x;
    if (t < NE) {
        int s = e_src(ei, t);
        int d = e_dst(ei, t);
        if ((unsigned)s < NN && (unsigned)d < NN) {
            int slot = atomicAdd(&g_pos[d], 1);
            g_cs[slot] = s;
            g_cc[slot] = g_dinv[s] * g_dinv[d];
        }
    }
}

// -------- GEMM1: h1[NN,128] = x[NN,256] @ W1[256,128] --------
__global__ void k_gemm1(const float* __restrict__ X, const float* __restrict__ W) {
    __shared__ __align__(16) float As[64][32];
    __shared__ __align__(16) float4 Bs[32 * 32];  // [k][c4]
    int tid = threadIdx.x;
    int r0 = blockIdx.x * 64;
    int tx = tid & 31;   // col group: 4 cols (float4)
    int ty = tid >> 5;   // row group: 8 rows
    float4 acc[8];
#pragma unroll
    for (int i = 0; i < 8; i++) acc[i] = make_float4(0.f, 0.f, 0.f, 0.f);

    for (int kt = 0; kt < DIN; kt += 32) {
#pragma unroll
        for (int q = 0; q < 2; q++) {
            int id = tid * 2 + q;
            int row = id >> 3, c4 = id & 7;
            float4 v = make_float4(0.f, 0.f, 0.f, 0.f);
            if (r0 + row < NN)
                v = *(const float4*)(X + (size_t)(r0 + row) * DIN + kt + c4 * 4);
            ((float4*)As)[row * 8 + c4] = v;
        }
#pragma unroll
        for (int q = 0; q < 4; q++) {
            int id = tid + q * 256;
            int k = id >> 5, c4 = id & 31;
            Bs[k * 32 + c4] = *(const float4*)(W + (size_t)(kt + k) * DH + c4 * 4);
        }
        __syncthreads();
#pragma unroll
        for (int k = 0; k < 32; k++) {
            float4 b = Bs[k * 32 + tx];
#pragma unroll
            for (int r = 0; r < 8; r++) {
                float a = As[ty * 8 + r][k];
                acc[r].x += a * b.x; acc[r].y += a * b.y;
                acc[r].z += a * b.z; acc[r].w += a * b.w;
            }
        }
        __syncthreads();
    }
#pragma unroll
    for (int r = 0; r < 8; r++) {
        int row = r0 + ty * 8 + r;
        if (row < NN)
            *(float4*)(g_h1 + (size_t)row * DH + tx * 4) = acc[r];
    }
}

// -------- layer1 aggregation: warp per node, CSR gather (no atomics) --------
__global__ void k_agg1() {
    int t = blockIdx.x * blockDim.x + threadIdx.x;
    int w = t >> 5, lane = t & 31;
    if (w >= NN) return;
    float dv = g_dinv[w];
    float c0 = dv * dv;
    const float4* H = (const float4*)g_h1;
    float4 acc = H[(size_t)w * 32 + lane];
    acc.x *= c0; acc.y *= c0; acc.z *= c0; acc.w *= c0;
    int beg = g_off[w];
    int end = beg + g_deg[w];
    for (int j = beg; j < end; j++) {
        int s = g_cs[j];          // converged -> broadcast
        float c = g_cc[j];
        float4 v = H[(size_t)s * 32 + lane];
        acc.x += c * v.x; acc.y += c * v.y;
        acc.z += c * v.z; acc.w += c * v.w;
    }
    ((float4*)g_a1)[(size_t)w * 32 + lane] = acc;
}

// -------- GEMM2: h2[NN,40] = relu(a1+b1)[NN,128] @ W2[128,40] --------
__global__ void k_gemm2(const float* __restrict__ W2, const float* __restrict__ B1) {
    __shared__ __align__(16) float As[128][65];
    __shared__ float Bs[64][40];
    int tid = threadIdx.x;
    int r0 = blockIdx.x * 128;
    int tx = tid & 7;    // col group: 5 cols
    int ty = tid >> 3;   // row group: 4 rows
    float acc[4][5];
#pragma unroll
    for (int i = 0; i < 4; i++)
#pragma unroll
        for (int c = 0; c < 5; c++) acc[i][c] = 0.f;

    for (int kt = 0; kt < DH; kt += 64) {
#pragma unroll
        for (int q = 0; q < 8; q++) {
            int id = tid + q * 256;
            int row = id >> 4, c4 = id & 15;
            float4 v = make_float4(0.f, 0.f, 0.f, 0.f);
            if (r0 + row < NN) {
                v = *(const float4*)(g_a1 + (size_t)(r0 + row) * DH + kt + c4 * 4);
                float4 bb = *(const float4*)(B1 + kt + c4 * 4);
                v.x = fmaxf(v.x + bb.x, 0.f); v.y = fmaxf(v.y + bb.y, 0.f);
                v.z = fmaxf(v.z + bb.z, 0.f); v.w = fmaxf(v.w + bb.w, 0.f);
            }
            As[row][c4 * 4 + 0] = v.x; As[row][c4 * 4 + 1] = v.y;
            As[row][c4 * 4 + 2] = v.z; As[row][c4 * 4 + 3] = v.w;
        }
#pragma unroll
        for (int q = 0; q < 10; q++) {
            int id = tid + q * 256;
            int k = id / 40, c = id % 40;
            Bs[k][c] = W2[(size_t)(kt + k) * DO + c];
        }
        __syncthreads();
#pragma unroll 8
        for (int k = 0; k < 64; k++) {
            float b[5];
#pragma unroll
            for (int c = 0; c < 5; c++) b[c] = Bs[k][tx * 5 + c];
#pragma unroll
            for (int i = 0; i < 4; i++) {
                float a = As[ty * 4 + i][k];
#pragma unroll
                for (int c = 0; c < 5; c++) acc[i][c] += a * b[c];
            }
        }
        __syncthreads();
    }
#pragma unroll
    for (int i = 0; i < 4; i++) {
        int row = r0 + ty * 4 + i;
        if (row < NN) {
#pragma unroll
            for (int c = 0; c < 5; c++)
                g_h2[(size_t)row * DO + tx * 5 + c] = acc[i][c];
        }
    }
}

// -------- layer2 aggregation: warp per node, CSR gather --------
__global__ void k_agg2(float* __restrict__ out) {
    int t = blockIdx.x * blockDim.x + threadIdx.x;
    int w = t >> 5, lane = t & 31;
    if (w >= NN) return;
    float dv = g_dinv[w];
    float c0 = dv * dv;
    const float* H = g_h2;
    float acc0 = c0 * H[(size_t)w * DO + lane];
    float acc1 = (lane < 8) ? c0 * H[(size_t)w * DO + 32 + lane] : 0.f;
    int beg = g_off[w];
    int end = beg + g_deg[w];
    for (int j = beg; j < end; j++) {
        int s = g_cs[j];
        float c = g_cc[j];
        acc0 += c * H[(size_t)s * DO + lane];
        if (lane < 8) acc1 += c * H[(size_t)s * DO + 32 + lane];
    }
    out[(size_t)w * DO + lane] = acc0;
    if (lane < 8) out[(size_t)w * DO + 32 + lane] = acc1;
}

// -------- log_softmax over 40 cols, one warp per row; fuse +b2 --------
__global__ void k_logsm(float* __restrict__ out, const float* __restrict__ B2) {
    int t = blockIdx.x * blockDim.x + threadIdx.x;
    int row = t >> 5, lane = t & 31;
    if (row >= NN) return;
    float* p = out + (size_t)row * DO;
    float v0 = p[lane] + B2[lane];
    float v1 = (lane < 8) ? (p[32 + lane] + B2[32 + lane]) : __int_as_float(0xff800000);
    float m = fmaxf(v0, v1);
#pragma unroll
    for (int o = 16; o > 0; o >>= 1) m = fmaxf(m, __shfl_xor_sync(0xffffffffu, m, o));
    float e0 = expf(v0 - m);
    float e1 = (lane < 8) ? expf(v1 - m) : 0.f;
    float s = e0 + e1;
#pragma unroll
    for (int o = 16; o > 0; o >>= 1) s += __shfl_xor_sync(0xffffffffu, s, o);
    float lse = m + logf(s);
    p[lane] = v0 - lse;
    if (lane < 8) p[32 + lane] = v1 - lse;
}

// -------- launch --------
extern "C" void kernel_launch(void* const* d_in, const int* in_sizes, int n_in,
                              void* d_out, int out_size) {
    const float* x  = (const float*)d_in[0];
    const void*  ei = d_in[1];
    const float* W1 = (const float*)d_in[2];
    const float* b1 = (const float*)d_in[3];
    const float* W2 = (const float*)d_in[4];
    const float* b2 = (const float*)d_in[5];
    float* out = (float*)d_out;

    (void)in_sizes; (void)n_in; (void)out_size;

    k_detect<<<1, 256>>>((const int*)ei);
    k_zero_deg<<<(NN + 255) / 256, 256>>>();
    k_deg<<<(NE + 255) / 256, 256>>>(ei);
    k_dinv<<<(NN + 255) / 256, 256>>>();

    k_scan_block<<<SCAN_NB, SCAN_BLK>>>();
    k_scan_top<<<1, 128>>>();
    k_scan_fix<<<(NN + 255) / 256, 256>>>();
    k_scatter<<<(NE + 255) / 256, 256>>>(ei);

    k_gemm1<<<(NN + 63) / 64, 256>>>(x, W1);
    k_agg1<<<(int)(((size_t)NN * 32 + 255) / 256), 256>>>();

    k_gemm2<<<(NN + 127) / 128, 256>>>(W2, b1);
    k_agg2<<<(int)(((size_t)NN * 32 + 255) / 256), 256>>>(out);

    k_logsm<<<(int)(((size_t)NN * 32 + 255) / 256), 256>>>(out, b2);
}

// round 4
// speedup vs baseline: 1.0140x; 1.0140x over previous
#include <cuda_runtime.h>
#include <cuda_fp16.h>
#include <cstdint>

#define NN 50000
#define NE 1600000
#define DIN 256
#define DH 128
#define DO 40

#define SCAN_BLK 512
#define SCAN_NB ((NN + SCAN_BLK - 1) / SCAN_BLK)   // 98

// -------- scratch (static device globals; no allocation allowed) --------
static __device__ __align__(16) float  g_h1[(size_t)NN * DH];    // x @ W1 (fp32)
static __device__ __align__(16) __half g_h1h[(size_t)NN * DH];   // fp16 copy for gather
static __device__ __align__(16) float  g_a1[(size_t)NN * DH];    // aggregated layer1
static __device__ __align__(16) float  g_h2[(size_t)NN * DO];    // layer2 pre-agg (fp32)
static __device__ __align__(16) __half g_h2h[(size_t)NN * DO];   // fp16 copy for gather
static __device__ int   g_deg[NN];
static __device__ float g_dinv[NN];
static __device__ int   g_off[NN];
static __device__ int   g_pos[NN];
static __device__ int   g_inc[SCAN_NB * SCAN_BLK];
static __device__ int   g_bsum[SCAN_NB];
static __device__ int   g_boff[SCAN_NB];
static __device__ int   g_cs[NE];
static __device__ float g_cc[NE];
static __device__ int   g_is64;

// -------- edge index accessors (dtype-agnostic) --------
__device__ __forceinline__ int e_src(const void* ei, int t) {
    return g_is64 ? (int)((const long long*)ei)[t] : ((const int*)ei)[t];
}
__device__ __forceinline__ int e_dst(const void* ei, int t) {
    return g_is64 ? (int)((const long long*)ei)[NE + t] : ((const int*)ei)[NE + t];
}

__global__ void k_detect(const int* __restrict__ ei32) {
    int t = threadIdx.x;
    if (t == 0) g_is64 = 1;
    __syncthreads();
    int any = 0;
    for (int i = t; i < 2048; i += blockDim.x) any |= ei32[2 * i + 1];
    if (any) g_is64 = 0;
}

// -------- degree / normalization --------
__global__ void k_zero_deg() {
    int t = blockIdx.x * blockDim.x + threadIdx.x;
    if (t < NN) g_deg[t] = 0;
}

__global__ void k_deg(const void* __restrict__ ei) {
    int t = blockIdx.x * blockDim.x + threadIdx.x;
    if (t < NE) {
        int d = e_dst(ei, t);
        if ((unsigned)d < NN) atomicAdd(&g_deg[d], 1);
    }
}

__global__ void k_dinv() {
    int t = blockIdx.x * blockDim.x + threadIdx.x;
    if (t < NN) g_dinv[t] = rsqrtf((float)(g_deg[t] + 1));
}

// -------- two-level exclusive scan --------
__global__ void k_scan_block() {
    __shared__ int sh[SCAN_BLK];
    int t = threadIdx.x;
    int i = blockIdx.x * SCAN_BLK + t;
    int v = (i < NN) ? g_deg[i] : 0;
    sh[t] = v;
    __syncthreads();
#pragma unroll
    for (int o = 1; o < SCAN_BLK; o <<= 1) {
        int x = (t >= o) ? sh[t - o] : 0;
        __syncthreads();
        sh[t] += x;
        __syncthreads();
    }
    g_inc[i] = sh[t];
    if (t == SCAN_BLK - 1) g_bsum[blockIdx.x] = sh[t];
}

__global__ void k_scan_top() {
    __shared__ int sh[128];
    int t = threadIdx.x;
    int v = (t < SCAN_NB) ? g_bsum[t] : 0;
    sh[t] = v;
    __syncthreads();
#pragma unroll
    for (int o = 1; o < 128; o <<= 1) {
        int x = (t >= o) ? sh[t - o] : 0;
        __syncthreads();
        sh[t] += x;
        __syncthreads();
    }
    if (t < SCAN_NB) g_boff[t] = sh[t] - v;
}

__global__ void k_scan_fix() {
    int t = blockIdx.x * blockDim.x + threadIdx.x;
    if (t < NN) {
        int off = g_inc[t] - g_deg[t] + g_boff[t / SCAN_BLK];
        g_off[t] = off;
        g_pos[t] = off;
    }
}

__global__ void k_scatter(const void* __restrict__ ei) {
    int t = blockIdx.x * blockDim.x + threadIdx.x;
    if (t < NE) {
        int s = e_src(ei, t);
        int d = e_dst(ei, t);
        if ((unsigned)s < NN && (unsigned)d < NN) {
            int slot = atomicAdd(&g_pos[d], 1);
            g_cs[slot] = s;
            g_cc[slot] = g_dinv[s] * g_dinv[d];
        }
    }
}

// -------- tf32 helpers --------
__device__ __forceinline__ uint32_t to_tf32(float x) {
    uint32_t r;
    asm("cvt.rna.tf32.f32 %0, %1;" : "=r"(r) : "f"(x));
    return r;
}

__device__ __forceinline__ void mma_tf32(float& d0, float& d1, float& d2, float& d3,
                                         uint32_t a0, uint32_t a1, uint32_t a2, uint32_t a3,
                                         uint32_t b0, uint32_t b1) {
    asm volatile(
        "mma.sync.aligned.m16n8k8.row.col.f32.tf32.tf32.f32 "
        "{%0,%1,%2,%3}, {%4,%5,%6,%7}, {%8,%9}, {%0,%1,%2,%3};"
        : "+f"(d0), "+f"(d1), "+f"(d2), "+f"(d3)
        : "r"(a0), "r"(a1), "r"(a2), "r"(a3), "r"(b0), "r"(b1));
}

// -------- GEMM1 (tensor core, 3xTF32): h1[NN,128] = X[NN,256] @ W[256,128] --------
// BM=128, BN=128(full), BK=16, 256 threads (8 warps: 4 in M x 2 in N).
// Each warp: 32 rows x 64 cols = 2 m-tiles(16) x 8 n-tiles(8).
#define LDA 20    // A smem row stride (floats): banks 4g+t bijective
#define LDB 136   // B smem row stride (floats): banks 8t+g bijective
__global__ void __launch_bounds__(256, 2)
k_gemm1(const float* __restrict__ X, const float* __restrict__ W) {
    __shared__ __align__(16) uint32_t Ah[128 * LDA];
    __shared__ __align__(16) uint32_t Al[128 * LDA];
    __shared__ __align__(16) uint32_t Bh[16 * LDB];
    __shared__ __align__(16) uint32_t Bl[16 * LDB];

    int tid = threadIdx.x;
    int lane = tid & 31;
    int wid = tid >> 5;
    int wm = wid & 3;            // warp row group (x32)
    int wn = wid >> 2;           // warp col group (x64)
    int g = lane >> 2;           // groupID
    int t = lane & 3;            // threadID_in_group
    int r0 = blockIdx.x * 128;

    float acc[2][8][4];
#pragma unroll
    for (int i = 0; i < 2; i++)
#pragma unroll
        for (int j = 0; j < 8; j++)
#pragma unroll
            for (int k = 0; k < 4; k++) acc[i][j][k] = 0.f;

    for (int kt = 0; kt < DIN; kt += 16) {
        // ---- stage X tile [128 x 16] as hi/lo tf32 ----
#pragma unroll
        for (int q = 0; q < 2; q++) {
            int id = tid + q * 256;
            int row = id >> 2, c4 = id & 3;
            float4 v = make_float4(0.f, 0.f, 0.f, 0.f);
            if (r0 + row < NN)
                v = *(const float4*)(X + (size_t)(r0 + row) * DIN + kt + c4 * 4);
            uint32_t h0 = to_tf32(v.x), h1 = to_tf32(v.y), h2 = to_tf32(v.z), h3 = to_tf32(v.w);
            uint32_t l0 = to_tf32(v.x - __uint_as_float(h0));
            uint32_t l1 = to_tf32(v.y - __uint_as_float(h1));
            uint32_t l2 = to_tf32(v.z - __uint_as_float(h2));
            uint32_t l3 = to_tf32(v.w - __uint_as_float(h3));
            uint4* ph = (uint4*)(Ah + row * LDA + c4 * 4);
            uint4* pl = (uint4*)(Al + row * LDA + c4 * 4);
            *ph = make_uint4(h0, h1, h2, h3);
            *pl = make_uint4(l0, l1, l2, l3);
        }
        // ---- stage W tile [16 x 128] as hi/lo tf32 ----
#pragma unroll
        for (int q = 0; q < 2; q++) {
            int id = tid + q * 256;
            int kr = id >> 5, c4 = id & 31;
            float4 v = *(const float4*)(W + (size_t)(kt + kr) * DH + c4 * 4);
            uint32_t h0 = to_tf32(v.x), h1 = to_tf32(v.y), h2 = to_tf32(v.z), h3 = to_tf32(v.w);
            uint32_t l0 = to_tf32(v.x - __uint_as_float(h0));
            uint32_t l1 = to_tf32(v.y - __uint_as_float(h1));
            uint32_t l2 = to_tf32(v.z - __uint_as_float(h2));
            uint32_t l3 = to_tf32(v.w - __uint_as_float(h3));
            *(uint4*)(Bh + kr * LDB + c4 * 4) = make_uint4(h0, h1, h2, h3);
            *(uint4*)(Bl + kr * LDB + c4 * 4) = make_uint4(l0, l1, l2, l3);
        }
        __syncthreads();

#pragma unroll
        for (int kk = 0; kk < 2; kk++) {   // two k8 steps per BK=16
            int kb = kk * 8;
            // A fragments (2 m-tiles, hi+lo)
            uint32_t ah[2][4], al[2][4];
#pragma unroll
            for (int mt = 0; mt < 2; mt++) {
                int rbase = (wm * 32 + mt * 16) * LDA + kb + t;
                ah[mt][0] = Ah[rbase + g * LDA];
                ah[mt][1] = Ah[rbase + (g + 8) * LDA];
                ah[mt][2] = Ah[rbase + g * LDA + 4];
                ah[mt][3] = Ah[rbase + (g + 8) * LDA + 4];
                al[mt][0] = Al[rbase + g * LDA];
                al[mt][1] = Al[rbase + (g + 8) * LDA];
                al[mt][2] = Al[rbase + g * LDA + 4];
                al[mt][3] = Al[rbase + (g + 8) * LDA + 4];
            }
            // B fragments (8 n-tiles, hi+lo)
            uint32_t bh[8][2], bl[8][2];
#pragma unroll
            for (int nt = 0; nt < 8; nt++) {
                int cbase = wn * 64 + nt * 8 + g;
                bh[nt][0] = Bh[(kb + t) * LDB + cbase];
                bh[nt][1] = Bh[(kb + t + 4) * LDB + cbase];
                bl[nt][0] = Bl[(kb + t) * LDB + cbase];
                bl[nt][1] = Bl[(kb + t + 4) * LDB + cbase];
            }
#pragma unroll
            for (int mt = 0; mt < 2; mt++)
#pragma unroll
                for (int nt = 0; nt < 8; nt++) {
                    float* d = acc[mt][nt];
                    mma_tf32(d[0], d[1], d[2], d[3],
                             ah[mt][0], ah[mt][1], ah[mt][2], ah[mt][3],
                             bh[nt][0], bh[nt][1]);
                    mma_tf32(d[0], d[1], d[2], d[3],
                             al[mt][0], al[mt][1], al[mt][2], al[mt][3],
                             bh[nt][0], bh[nt][1]);
                    mma_tf32(d[0], d[1], d[2], d[3],
                             ah[mt][0], ah[mt][1], ah[mt][2], ah[mt][3],
                             bl[nt][0], bl[nt][1]);
                }
        }
        __syncthreads();
    }

    // ---- epilogue: write fp32 h1 and fp16 copy ----
#pragma unroll
    for (int mt = 0; mt < 2; mt++) {
#pragma unroll
        for (int nt = 0; nt < 8; nt++) {
            int col = wn * 64 + nt * 8 + 2 * t;
            int rowa = r0 + wm * 32 + mt * 16 + g;
            int rowb = rowa + 8;
            float* d = acc[mt][nt];
            if (rowa < NN) {
                *(float2*)(g_h1 + (size_t)rowa * DH + col) = make_float2(d[0], d[1]);
                *(__half2*)(g_h1h + (size_t)rowa * DH + col) = __floats2half2_rn(d[0], d[1]);
            }
            if (rowb < NN) {
                *(float2*)(g_h1 + (size_t)rowb * DH + col) = make_float2(d[2], d[3]);
                *(__half2*)(g_h1h + (size_t)rowb * DH + col) = __floats2half2_rn(d[2], d[3]);
            }
        }
    }
}

// -------- layer1 aggregation: warp per node, fp16 gather, fp32 accumulate --------
__global__ void k_agg1() {
    int t = blockIdx.x * blockDim.x + threadIdx.x;
    int w = t >> 5, lane = t & 31;
    if (w >= NN) return;
    float dv = g_dinv[w];
    float c0 = dv * dv;
    // self term from fp32 copy
    float4 acc = ((const float4*)g_h1)[(size_t)w * 32 + lane];
    acc.x *= c0; acc.y *= c0; acc.z *= c0; acc.w *= c0;
    const uint2* Hh = (const uint2*)g_h1h;   // 4 halfs per lane (cols 4*lane..4*lane+3)
    int beg = g_off[w];
    int end = beg + g_deg[w];
    for (int j = beg; j < end; j++) {
        int s = g_cs[j];
        float c = g_cc[j];
        uint2 u = Hh[(size_t)s * 32 + lane];
        float2 f0 = __half22float2(*(__half2*)&u.x);
        float2 f1 = __half22float2(*(__half2*)&u.y);
        acc.x += c * f0.x; acc.y += c * f0.y;
        acc.z += c * f1.x; acc.w += c * f1.y;
    }
    ((float4*)g_a1)[(size_t)w * 32 + lane] = acc;
}

// -------- GEMM2: h2[NN,40] = relu(a1+b1)[NN,128] @ W2[128,40] --------
__global__ void k_gemm2(const float* __restrict__ W2, const float* __restrict__ B1) {
    __shared__ __align__(16) float As[128][65];
    __shared__ float Bs[64][40];
    int tid = threadIdx.x;
    int r0 = blockIdx.x * 128;
    int tx = tid & 7;
    int ty = tid >> 3;
    float acc[4][5];
#pragma unroll
    for (int i = 0; i < 4; i++)
#pragma unroll
        for (int c = 0; c < 5; c++) acc[i][c] = 0.f;

    for (int kt = 0; kt < DH; kt += 64) {
#pragma unroll
        for (int q = 0; q < 8; q++) {
            int id = tid + q * 256;
            int row = id >> 4, c4 = id & 15;
            float4 v = make_float4(0.f, 0.f, 0.f, 0.f);
            if (r0 + row < NN) {
                v = *(const float4*)(g_a1 + (size_t)(r0 + row) * DH + kt + c4 * 4);
                float4 bb = *(const float4*)(B1 + kt + c4 * 4);
                v.x = fmaxf(v.x + bb.x, 0.f); v.y = fmaxf(v.y + bb.y, 0.f);
                v.z = fmaxf(v.z + bb.z, 0.f); v.w = fmaxf(v.w + bb.w, 0.f);
            }
            As[row][c4 * 4 + 0] = v.x; As[row][c4 * 4 + 1] = v.y;
            As[row][c4 * 4 + 2] = v.z; As[row][c4 * 4 + 3] = v.w;
        }
#pragma unroll
        for (int q = 0; q < 10; q++) {
            int id = tid + q * 256;
            int k = id / 40, c = id % 40;
            Bs[k][c] = W2[(size_t)(kt + k) * DO + c];
        }
        __syncthreads();
#pragma unroll 8
        for (int k = 0; k < 64; k++) {
            float b[5];
#pragma unroll
            for (int c = 0; c < 5; c++) b[c] = Bs[k][tx * 5 + c];
#pragma unroll
            for (int i = 0; i < 4; i++) {
                float a = As[ty * 4 + i][k];
#pragma unroll
                for (int c = 0; c < 5; c++) acc[i][c] += a * b[c];
            }
        }
        __syncthreads();
    }
#pragma unroll
    for (int i = 0; i < 4; i++) {
        int row = r0 + ty * 4 + i;
        if (row < NN) {
#pragma unroll
            for (int c = 0; c < 5; c++) {
                g_h2[(size_t)row * DO + tx * 5 + c] = acc[i][c];
                g_h2h[(size_t)row * DO + tx * 5 + c] = __float2half_rn(acc[i][c]);
            }
        }
    }
}

// -------- layer2 aggregation: warp per node, fp16 gather --------
// lanes 0..19 each handle cols {2*lane, 2*lane+1}
__global__ void k_agg2(float* __restrict__ out) {
    int t = blockIdx.x * blockDim.x + threadIdx.x;
    int w = t >> 5, lane = t & 31;
    if (w >= NN || lane >= 20) return;
    float dv = g_dinv[w];
    float c0 = dv * dv;
    float acc0 = c0 * g_h2[(size_t)w * DO + 2 * lane];
    float acc1 = c0 * g_h2[(size_t)w * DO + 2 * lane + 1];
    const __half2* Hh = (const __half2*)g_h2h;
    int beg = g_off[w];
    int end = beg + g_deg[w];
    for (int j = beg; j < end; j++) {
        int s = g_cs[j];
        float c = g_cc[j];
        float2 f = __half22float2(Hh[(size_t)s * 20 + lane]);
        acc0 += c * f.x;
        acc1 += c * f.y;
    }
    *(float2*)(out + (size_t)w * DO + 2 * lane) = make_float2(acc0, acc1);
}

// -------- log_softmax over 40 cols, one warp per row; fuse +b2 --------
__global__ void k_logsm(float* __restrict__ out, const float* __restrict__ B2) {
    int t = blockIdx.x * blockDim.x + threadIdx.x;
    int row = t >> 5, lane = t & 31;
    if (row >= NN) return;
    float* p = out + (size_t)row * DO;
    float v0 = p[lane] + B2[lane];
    float v1 = (lane < 8) ? (p[32 + lane] + B2[32 + lane]) : __int_as_float(0xff800000);
    float m = fmaxf(v0, v1);
#pragma unroll
    for (int o = 16; o > 0; o >>= 1) m = fmaxf(m, __shfl_xor_sync(0xffffffffu, m, o));
    float e0 = expf(v0 - m);
    float e1 = (lane < 8) ? expf(v1 - m) : 0.f;
    float s = e0 + e1;
#pragma unroll
    for (int o = 16; o > 0; o >>= 1) s += __shfl_xor_sync(0xffffffffu, s, o);
    float lse = m + logf(s);
    p[lane] = v0 - lse;
    if (lane < 8) p[32 + lane] = v1 - lse;
}

// -------- launch --------
extern "C" void kernel_launch(void* const* d_in, const int* in_sizes, int n_in,
                              void* d_out, int out_size) {
    const float* x  = (const float*)d_in[0];
    const void*  ei = d_in[1];
    const float* W1 = (const float*)d_in[2];
    const float* b1 = (const float*)d_in[3];
    const float* W2 = (const float*)d_in[4];
    const float* b2 = (const float*)d_in[5];
    float* out = (float*)d_out;

    (void)in_sizes; (void)n_in; (void)out_size;

    k_detect<<<1, 256>>>((const int*)ei);
    k_zero_deg<<<(NN + 255) / 256, 256>>>();
    k_deg<<<(NE + 255) / 256, 256>>>(ei);
    k_dinv<<<(NN + 255) / 256, 256>>>();

    k_scan_block<<<SCAN_NB, SCAN_BLK>>>();
    k_scan_top<<<1, 128>>>();
    k_scan_fix<<<(NN + 255) / 256, 256>>>();
    k_scatter<<<(NE + 255) / 256, 256>>>(ei);

    k_gemm1<<<(NN + 127) / 128, 256>>>(x, W1);
    k_agg1<<<(int)(((size_t)NN * 32 + 255) / 256), 256>>>();

    k_gemm2<<<(NN + 127) / 128, 256>>>(W2, b1);
    k_agg2<<<(int)(((size_t)NN * 32 + 255) / 256), 256>>>(out);

    k_logsm<<<(int)(((size_t)NN * 32 + 255) / 256), 256>>>(out, b2);
}

// round 5
// speedup vs baseline: 1.0682x; 1.0534x over previous
#include <cuda_runtime.h>
#include <cuda_fp16.h>
#include <cstdint>

#define NN 50000
#define NE 1600000
#define DIN 256
#define DH 128
#define DO 40

#define SCAN_BLK 512
#define SCAN_NB ((NN + SCAN_BLK - 1) / SCAN_BLK)   // 98

// -------- scratch (static device globals; no allocation allowed) --------
static __device__ __align__(16) __half g_h1h[(size_t)NN * DH];   // x@W1 (fp16, gather source)
static __device__ __align__(16) float  g_a1[(size_t)NN * DH];    // aggregated layer1 (fp32)
static __device__ __align__(16) __half g_h2h[(size_t)NN * DO];   // layer2 pre-agg (fp16)
static __device__ int   g_deg[NN];
static __device__ float g_dinv[NN];
static __device__ int   g_off[NN];
static __device__ int   g_pos[NN];
static __device__ int   g_inc[SCAN_NB * SCAN_BLK];
static __device__ int   g_bsum[SCAN_NB];
static __device__ int2  g_edge[NE];    // packed CSR slot: {src, coef as float bits}
static __device__ int   g_is64;

// -------- edge index accessors (dtype-agnostic) --------
__device__ __forceinline__ int e_src(const void* ei, int t) {
    return g_is64 ? (int)((const long long*)ei)[t] : ((const int*)ei)[t];
}
__device__ __forceinline__ int e_dst(const void* ei, int t) {
    return g_is64 ? (int)((const long long*)ei)[NE + t] : ((const int*)ei)[NE + t];
}

// -------- init: zero degree counters + detect edge dtype --------
__global__ void k_init(const int* __restrict__ ei32) {
    if (blockIdx.x == gridDim.x - 1) {
        int t = threadIdx.x;
        if (t == 0) g_is64 = 1;
        __syncthreads();
        int any = 0;
        for (int i = t; i < 2048; i += blockDim.x) any |= ei32[2 * i + 1];
        if (any) g_is64 = 0;
        return;
    }
    int t = blockIdx.x * blockDim.x + threadIdx.x;
    if (t < NN) g_deg[t] = 0;
}

__global__ void k_deg(const void* __restrict__ ei) {
    int t = blockIdx.x * blockDim.x + threadIdx.x;
    if (t < NE) {
        int d = e_dst(ei, t);
        if ((unsigned)d < NN) atomicAdd(&g_deg[d], 1);
    }
}

// -------- scan level 1: per-block inclusive scan --------
__global__ void k_scan_block() {
    __shared__ int sh[SCAN_BLK];
    int t = threadIdx.x;
    int i = blockIdx.x * SCAN_BLK + t;
    int v = (i < NN) ? g_deg[i] : 0;
    sh[t] = v;
    __syncthreads();
#pragma unroll
    for (int o = 1; o < SCAN_BLK; o <<= 1) {
        int x = (t >= o) ? sh[t - o] : 0;
        __syncthreads();
        sh[t] += x;
        __syncthreads();
    }
    g_inc[i] = sh[t];
    if (t == SCAN_BLK - 1) g_bsum[blockIdx.x] = sh[t];
}

// -------- scan fix (+ top scan in-block) + dinv --------
__global__ void k_scan_fix() {
    __shared__ int sb[SCAN_NB];
    if (threadIdx.x == 0) {
        int run = 0;
        for (int i = 0; i < SCAN_NB; i++) { sb[i] = run; run += g_bsum[i]; }
    }
    __syncthreads();
    int t = blockIdx.x * blockDim.x + threadIdx.x;
    if (t < NN) {
        int dg = g_deg[t];
        int off = g_inc[t] - dg + sb[t / SCAN_BLK];  // exclusive
        g_off[t] = off;
        g_pos[t] = off;
        g_dinv[t] = rsqrtf((float)(dg + 1));
    }
}

// -------- CSR fill: packed (src, coef) --------
__global__ void k_scatter(const void* __restrict__ ei) {
    int t = blockIdx.x * blockDim.x + threadIdx.x;
    if (t < NE) {
        int s = e_src(ei, t);
        int d = e_dst(ei, t);
        if ((unsigned)s < NN && (unsigned)d < NN) {
            int slot = atomicAdd(&g_pos[d], 1);
            g_edge[slot] = make_int2(s, __float_as_int(g_dinv[s] * g_dinv[d]));
        }
    }
}

// -------- tf32 helpers --------
__device__ __forceinline__ uint32_t to_tf32(float x) {
    uint32_t r;
    asm("cvt.rna.tf32.f32 %0, %1;" : "=r"(r) : "f"(x));
    return r;
}

__device__ __forceinline__ void mma_tf32(float& d0, float& d1, float& d2, float& d3,
                                         uint32_t a0, uint32_t a1, uint32_t a2, uint32_t a3,
                                         uint32_t b0, uint32_t b1) {
    asm volatile(
        "mma.sync.aligned.m16n8k8.row.col.f32.tf32.tf32.f32 "
        "{%0,%1,%2,%3}, {%4,%5,%6,%7}, {%8,%9}, {%0,%1,%2,%3};"
        : "+f"(d0), "+f"(d1), "+f"(d2), "+f"(d3)
        : "r"(a0), "r"(a1), "r"(a2), "r"(a3), "r"(b0), "r"(b1));
}

// -------- GEMM1 (3xTF32): h1h[NN,128] = X[NN,256] @ W[256,128] --------
#define LDA 20
#define LDB 136
__global__ void __launch_bounds__(256, 2)
k_gemm1(const float* __restrict__ X, const float* __restrict__ W) {
    __shared__ __align__(16) uint32_t Ah[128 * LDA];
    __shared__ __align__(16) uint32_t Al[128 * LDA];
    __shared__ __align__(16) uint32_t Bh[16 * LDB];
    __shared__ __align__(16) uint32_t Bl[16 * LDB];

    int tid = threadIdx.x;
    int lane = tid & 31;
    int wid = tid >> 5;
    int wm = wid & 3;
    int wn = wid >> 2;
    int g = lane >> 2;
    int t = lane & 3;
    int r0 = blockIdx.x * 128;

    float acc[2][8][4];
#pragma unroll
    for (int i = 0; i < 2; i++)
#pragma unroll
        for (int j = 0; j < 8; j++)
#pragma unroll
            for (int k = 0; k < 4; k++) acc[i][j][k] = 0.f;

    for (int kt = 0; kt < DIN; kt += 16) {
#pragma unroll
        for (int q = 0; q < 2; q++) {
            int id = tid + q * 256;
            int row = id >> 2, c4 = id & 3;
            float4 v = make_float4(0.f, 0.f, 0.f, 0.f);
            if (r0 + row < NN)
                v = *(const float4*)(X + (size_t)(r0 + row) * DIN + kt + c4 * 4);
            uint32_t h0 = to_tf32(v.x), h1 = to_tf32(v.y), h2 = to_tf32(v.z), h3 = to_tf32(v.w);
            uint32_t l0 = to_tf32(v.x - __uint_as_float(h0));
            uint32_t l1 = to_tf32(v.y - __uint_as_float(h1));
            uint32_t l2 = to_tf32(v.z - __uint_as_float(h2));
            uint32_t l3 = to_tf32(v.w - __uint_as_float(h3));
            *(uint4*)(Ah + row * LDA + c4 * 4) = make_uint4(h0, h1, h2, h3);
            *(uint4*)(Al + row * LDA + c4 * 4) = make_uint4(l0, l1, l2, l3);
        }
#pragma unroll
        for (int q = 0; q < 2; q++) {
            int id = tid + q * 256;
            int kr = id >> 5, c4 = id & 31;
            float4 v = *(const float4*)(W + (size_t)(kt + kr) * DH + c4 * 4);
            uint32_t h0 = to_tf32(v.x), h1 = to_tf32(v.y), h2 = to_tf32(v.z), h3 = to_tf32(v.w);
            uint32_t l0 = to_tf32(v.x - __uint_as_float(h0));
            uint32_t l1 = to_tf32(v.y - __uint_as_float(h1));
            uint32_t l2 = to_tf32(v.z - __uint_as_float(h2));
            uint32_t l3 = to_tf32(v.w - __uint_as_float(h3));
            *(uint4*)(Bh + kr * LDB + c4 * 4) = make_uint4(h0, h1, h2, h3);
            *(uint4*)(Bl + kr * LDB + c4 * 4) = make_uint4(l0, l1, l2, l3);
        }
        __syncthreads();

#pragma unroll
        for (int kk = 0; kk < 2; kk++) {
            int kb = kk * 8;
            uint32_t ah[2][4], al[2][4];
#pragma unroll
            for (int mt = 0; mt < 2; mt++) {
                int rbase = (wm * 32 + mt * 16) * LDA + kb + t;
                ah[mt][0] = Ah[rbase + g * LDA];
                ah[mt][1] = Ah[rbase + (g + 8) * LDA];
                ah[mt][2] = Ah[rbase + g * LDA + 4];
                ah[mt][3] = Ah[rbase + (g + 8) * LDA + 4];
                al[mt][0] = Al[rbase + g * LDA];
                al[mt][1] = Al[rbase + (g + 8) * LDA];
                al[mt][2] = Al[rbase + g * LDA + 4];
                al[mt][3] = Al[rbase + (g + 8) * LDA + 4];
            }
            uint32_t bh[8][2], bl[8][2];
#pragma unroll
            for (int nt = 0; nt < 8; nt++) {
                int cbase = wn * 64 + nt * 8 + g;
                bh[nt][0] = Bh[(kb + t) * LDB + cbase];
                bh[nt][1] = Bh[(kb + t + 4) * LDB + cbase];
                bl[nt][0] = Bl[(kb + t) * LDB + cbase];
                bl[nt][1] = Bl[(kb + t + 4) * LDB + cbase];
            }
#pragma unroll
            for (int mt = 0; mt < 2; mt++)
#pragma unroll
                for (int nt = 0; nt < 8; nt++) {
                    float* d = acc[mt][nt];
                    mma_tf32(d[0], d[1], d[2], d[3],
                             ah[mt][0], ah[mt][1], ah[mt][2], ah[mt][3],
                             bh[nt][0], bh[nt][1]);
                    mma_tf32(d[0], d[1], d[2], d[3],
                             al[mt][0], al[mt][1], al[mt][2], al[mt][3],
                             bh[nt][0], bh[nt][1]);
                    mma_tf32(d[0], d[1], d[2], d[3],
                             ah[mt][0], ah[mt][1], ah[mt][2], ah[mt][3],
                             bl[nt][0], bl[nt][1]);
                }
        }
        __syncthreads();
    }

    // epilogue: fp16 only
#pragma unroll
    for (int mt = 0; mt < 2; mt++) {
#pragma unroll
        for (int nt = 0; nt < 8; nt++) {
            int col = wn * 64 + nt * 8 + 2 * t;
            int rowa = r0 + wm * 32 + mt * 16 + g;
            int rowb = rowa + 8;
            float* d = acc[mt][nt];
            if (rowa < NN)
                *(__half2*)(g_h1h + (size_t)rowa * DH + col) = __floats2half2_rn(d[0], d[1]);
            if (rowb < NN)
                *(__half2*)(g_h1h + (size_t)rowb * DH + col) = __floats2half2_rn(d[2], d[3]);
        }
    }
}

// -------- layer1 aggregation: warp per node, fp16 gather, fp32 accum, 2x unroll --------
__global__ void k_agg1() {
    int t = blockIdx.x * blockDim.x + threadIdx.x;
    int w = t >> 5, lane = t & 31;
    if (w >= NN) return;
    float dv = g_dinv[w];
    float c0 = dv * dv;
    const uint2* __restrict__ Hh = (const uint2*)g_h1h;
    // self term (fp16 source)
    uint2 us = Hh[(size_t)w * 32 + lane];
    float2 s0 = __half22float2(*(__half2*)&us.x);
    float2 s1 = __half22float2(*(__half2*)&us.y);
    float4 acc = make_float4(c0 * s0.x, c0 * s0.y, c0 * s1.x, c0 * s1.y);

    int j = g_off[w];
    int end = j + g_deg[w];
    for (; j + 2 <= end; j += 2) {
        int2 e0 = g_edge[j];
        int2 e1 = g_edge[j + 1];
        float ca = __int_as_float(e0.y);
        float cb = __int_as_float(e1.y);
        uint2 u0 = Hh[(size_t)e0.x * 32 + lane];
        uint2 u1 = Hh[(size_t)e1.x * 32 + lane];
        float2 a0 = __half22float2(*(__half2*)&u0.x);
        float2 a1 = __half22float2(*(__half2*)&u0.y);
        float2 b0 = __half22float2(*(__half2*)&u1.x);
        float2 b1 = __half22float2(*(__half2*)&u1.y);
        acc.x += ca * a0.x + cb * b0.x;
        acc.y += ca * a0.y + cb * b0.y;
        acc.z += ca * a1.x + cb * b1.x;
        acc.w += ca * a1.y + cb * b1.y;
    }
    if (j < end) {
        int2 e0 = g_edge[j];
        float ca = __int_as_float(e0.y);
        uint2 u0 = Hh[(size_t)e0.x * 32 + lane];
        float2 a0 = __half22float2(*(__half2*)&u0.x);
        float2 a1 = __half22float2(*(__half2*)&u0.y);
        acc.x += ca * a0.x; acc.y += ca * a0.y;
        acc.z += ca * a1.x; acc.w += ca * a1.y;
    }
    ((float4*)g_a1)[(size_t)w * 32 + lane] = acc;
}

// -------- GEMM2: h2h[NN,40] = relu(a1+b1)[NN,128] @ W2[128,40] --------
__global__ void k_gemm2(const float* __restrict__ W2, const float* __restrict__ B1) {
    __shared__ __align__(16) float As[128][65];
    __shared__ float Bs[64][40];
    int tid = threadIdx.x;
    int r0 = blockIdx.x * 128;
    int tx = tid & 7;
    int ty = tid >> 3;
    float acc[4][5];
#pragma unroll
    for (int i = 0; i < 4; i++)
#pragma unroll
        for (int c = 0; c < 5; c++) acc[i][c] = 0.f;

    for (int kt = 0; kt < DH; kt += 64) {
#pragma unroll
        for (int q = 0; q < 8; q++) {
            int id = tid + q * 256;
            int row = id >> 4, c4 = id & 15;
            float4 v = make_float4(0.f, 0.f, 0.f, 0.f);
            if (r0 + row < NN) {
                v = *(const float4*)(g_a1 + (size_t)(r0 + row) * DH + kt + c4 * 4);
                float4 bb = *(const float4*)(B1 + kt + c4 * 4);
                v.x = fmaxf(v.x + bb.x, 0.f); v.y = fmaxf(v.y + bb.y, 0.f);
                v.z = fmaxf(v.z + bb.z, 0.f); v.w = fmaxf(v.w + bb.w, 0.f);
            }
            As[row][c4 * 4 + 0] = v.x; As[row][c4 * 4 + 1] = v.y;
            As[row][c4 * 4 + 2] = v.z; As[row][c4 * 4 + 3] = v.w;
        }
#pragma unroll
        for (int q = 0; q < 10; q++) {
            int id = tid + q * 256;
            int k = id / 40, c = id % 40;
            Bs[k][c] = W2[(size_t)(kt + k) * DO + c];
        }
        __syncthreads();
#pragma unroll 8
        for (int k = 0; k < 64; k++) {
            float b[5];
#pragma unroll
            for (int c = 0; c < 5; c++) b[c] = Bs[k][tx * 5 + c];
#pragma unroll
            for (int i = 0; i < 4; i++) {
                float a = As[ty * 4 + i][k];
#pragma unroll
                for (int c = 0; c < 5; c++) acc[i][c] += a * b[c];
            }
        }
        __syncthreads();
    }
#pragma unroll
    for (int i = 0; i < 4; i++) {
        int row = r0 + ty * 4 + i;
        if (row < NN) {
#pragma unroll
            for (int c = 0; c < 5; c++)
                g_h2h[(size_t)row * DO + tx * 5 + c] = __float2half_rn(acc[i][c]);
        }
    }
}

// -------- layer2 aggregation + bias + log_softmax fused: warp per node --------
__global__ void k_agg2_logsm(float* __restrict__ out, const float* __restrict__ B2) {
    int t = blockIdx.x * blockDim.x + threadIdx.x;
    int w = t >> 5, lane = t & 31;
    if (w >= NN) return;
    bool act = lane < 20;
    float dv = g_dinv[w];
    float c0 = dv * dv;
    const __half2* __restrict__ Hh = (const __half2*)g_h2h;
    float acc0 = 0.f, acc1 = 0.f;
    if (act) {
        float2 f = __half22float2(Hh[(size_t)w * 20 + lane]);
        acc0 = c0 * f.x;
        acc1 = c0 * f.y;
    }
    int j = g_off[w];
    int end = j + g_deg[w];
    for (; j + 2 <= end; j += 2) {
        int2 e0 = g_edge[j];
        int2 e1 = g_edge[j + 1];
        if (act) {
            float ca = __int_as_float(e0.y);
            float cb = __int_as_float(e1.y);
            float2 f0 = __half22float2(Hh[(size_t)e0.x * 20 + lane]);
            float2 f1 = __half22float2(Hh[(size_t)e1.x * 20 + lane]);
            acc0 += ca * f0.x + cb * f1.x;
            acc1 += ca * f0.y + cb * f1.y;
        }
    }
    if (j < end) {
        int2 e0 = g_edge[j];
        if (act) {
            float ca = __int_as_float(e0.y);
            float2 f0 = __half22float2(Hh[(size_t)e0.x * 20 + lane]);
            acc0 += ca * f0.x;
            acc1 += ca * f0.y;
        }
    }
    // bias + log_softmax across 40 cols held by lanes 0..19
    if (act) {
        acc0 += B2[2 * lane];
        acc1 += B2[2 * lane + 1];
    }
    float m = act ? fmaxf(acc0, acc1) : __int_as_float(0xff800000);
#pragma unroll
    for (int o = 16; o > 0; o >>= 1) m = fmaxf(m, __shfl_xor_sync(0xffffffffu, m, o));
    float s = act ? (expf(acc0 - m) + expf(acc1 - m)) : 0.f;
#pragma unroll
    for (int o = 16; o > 0; o >>= 1) s += __shfl_xor_sync(0xffffffffu, s, o);
    float lse = m + logf(s);
    if (act)
        *(float2*)(out + (size_t)w * DO + 2 * lane) = make_float2(acc0 - lse, acc1 - lse);
}

// -------- launch --------
extern "C" void kernel_launch(void* const* d_in, const int* in_sizes, int n_in,
                              void* d_out, int out_size) {
    const float* x  = (const float*)d_in[0];
    const void*  ei = d_in[1];
    const float* W1 = (const float*)d_in[2];
    const float* b1 = (const float*)d_in[3];
    const float* W2 = (const float*)d_in[4];
    const float* b2 = (const float*)d_in[5];
    float* out = (float*)d_out;

    (void)in_sizes; (void)n_in; (void)out_size;

    k_init<<<(NN + 255) / 256 + 1, 256>>>((const int*)ei);          // 1
    k_deg<<<(NE + 255) / 256, 256>>>(ei);                           // 2
    k_scan_block<<<SCAN_NB, SCAN_BLK>>>();                          // 3
    k_gemm1<<<(NN + 127) / 128, 256>>>(x, W1);                      // 4  <- ncu capture slot
    k_scan_fix<<<(NN + 255) / 256, 256>>>();                        // 5
    k_scatter<<<(NE + 255) / 256, 256>>>(ei);                       // 6
    k_agg1<<<(int)(((size_t)NN * 32 + 255) / 256), 256>>>();        // 7
    k_gemm2<<<(NN + 127) / 128, 256>>>(W2, b1);                     // 8
    k_agg2_logsm<<<(int)(((size_t)NN * 32 + 255) / 256), 256>>>(out, b2);  // 9
}

// round 6
// speedup vs baseline: 1.3310x; 1.2460x over previous
#include <cuda_runtime.h>
#include <cuda_fp16.h>
#include <cstdint>

#define NN 50000
#define NE 1600000
#define DIN 256
#define DH 128
#define DO 40

#define SCAN_BLK 512
#define SCAN_NB ((NN + SCAN_BLK - 1) / SCAN_BLK)   // 98

// -------- scratch (static device globals; no allocation allowed) --------
static __device__ __align__(16) __half g_h1h[(size_t)NN * DH];   // x@W1 (fp16, gather source)
static __device__ __align__(16) __half g_a1h[(size_t)NN * DH];   // relu(agg1+b1) (fp16)
static __device__ __align__(16) __half g_h2h[(size_t)NN * DO];   // layer2 pre-agg (fp16)
static __device__ int      g_deg[NN];
static __device__ float    g_dinv[NN];
static __device__ int      g_off[NN];
static __device__ int      g_pos[NN];
static __device__ int      g_inc[SCAN_NB * SCAN_BLK];
static __device__ int      g_bsum[SCAN_NB];
static __device__ unsigned g_edge[NE];   // packed: (src << 16) | fp16(coef)
static __device__ int      g_is64;

// -------- edge index accessors (dtype-agnostic) --------
__device__ __forceinline__ int e_src(const void* ei, int t) {
    return g_is64 ? (int)((const long long*)ei)[t] : ((const int*)ei)[t];
}
__device__ __forceinline__ int e_dst(const void* ei, int t) {
    return g_is64 ? (int)((const long long*)ei)[NE + t] : ((const int*)ei)[NE + t];
}

// -------- init: zero degree counters + detect edge dtype --------
__global__ void k_init(const int* __restrict__ ei32) {
    if (blockIdx.x == gridDim.x - 1) {
        int t = threadIdx.x;
        if (t == 0) g_is64 = 1;
        __syncthreads();
        int any = 0;
        for (int i = t; i < 2048; i += blockDim.x) any |= ei32[2 * i + 1];
        if (any) g_is64 = 0;
        return;
    }
    int t = blockIdx.x * blockDim.x + threadIdx.x;
    if (t < NN) g_deg[t] = 0;
}

__global__ void k_deg(const void* __restrict__ ei) {
    int t = blockIdx.x * blockDim.x + threadIdx.x;
    if (t < NE) {
        int d = e_dst(ei, t);
        if ((unsigned)d < NN) atomicAdd(&g_deg[d], 1);
    }
}

// -------- scan level 1: per-block inclusive scan --------
__global__ void k_scan_block() {
    __shared__ int sh[SCAN_BLK];
    int t = threadIdx.x;
    int i = blockIdx.x * SCAN_BLK + t;
    int v = (i < NN) ? g_deg[i] : 0;
    sh[t] = v;
    __syncthreads();
#pragma unroll
    for (int o = 1; o < SCAN_BLK; o <<= 1) {
        int x = (t >= o) ? sh[t - o] : 0;
        __syncthreads();
        sh[t] += x;
        __syncthreads();
    }
    g_inc[i] = sh[t];
    if (t == SCAN_BLK - 1) g_bsum[blockIdx.x] = sh[t];
}

// -------- scan fix (+ in-block top scan) + dinv --------
__global__ void k_scan_fix() {
    __shared__ int sb[SCAN_NB];
    if (threadIdx.x == 0) {
        int run = 0;
        for (int i = 0; i < SCAN_NB; i++) { sb[i] = run; run += g_bsum[i]; }
    }
    __syncthreads();
    int t = blockIdx.x * blockDim.x + threadIdx.x;
    if (t < NN) {
        int dg = g_deg[t];
        int off = g_inc[t] - dg + sb[t / SCAN_BLK];  // exclusive
        g_off[t] = off;
        g_pos[t] = off;
        g_dinv[t] = rsqrtf((float)(dg + 1));
    }
}

// -------- CSR fill: packed (src:16 | coef:fp16) --------
__global__ void k_scatter(const void* __restrict__ ei) {
    int t = blockIdx.x * blockDim.x + threadIdx.x;
    if (t < NE) {
        int s = e_src(ei, t);
        int d = e_dst(ei, t);
        if ((unsigned)s < NN && (unsigned)d < NN) {
            int slot = atomicAdd(&g_pos[d], 1);
            unsigned hb = __half_as_ushort(__float2half_rn(g_dinv[s] * g_dinv[d]));
            g_edge[slot] = ((unsigned)s << 16) | hb;
        }
    }
}

__device__ __forceinline__ void unpack_edge(unsigned e, int& s, float& c) {
    s = (int)(e >> 16);
    c = __half2float(__ushort_as_half((unsigned short)(e & 0xffffu)));
}

// -------- tf32 helpers --------
__device__ __forceinline__ uint32_t to_tf32(float x) {
    uint32_t r;
    asm("cvt.rna.tf32.f32 %0, %1;" : "=r"(r) : "f"(x));
    return r;
}

__device__ __forceinline__ void mma_tf32(float& d0, float& d1, float& d2, float& d3,
                                         uint32_t a0, uint32_t a1, uint32_t a2, uint32_t a3,
                                         uint32_t b0, uint32_t b1) {
    asm volatile(
        "mma.sync.aligned.m16n8k8.row.col.f32.tf32.tf32.f32 "
        "{%0,%1,%2,%3}, {%4,%5,%6,%7}, {%8,%9}, {%0,%1,%2,%3};"
        : "+f"(d0), "+f"(d1), "+f"(d2), "+f"(d3)
        : "r"(a0), "r"(a1), "r"(a2), "r"(a3), "r"(b0), "r"(b1));
}

// -------- GEMM1 (1xTF32): h1h[NN,128] = X[NN,256] @ W[256,128] --------
#define LDA 20
#define LDB 136
__global__ void __launch_bounds__(256)
k_gemm1(const float* __restrict__ X, const float* __restrict__ W) {
    __shared__ __align__(16) uint32_t Ah[128 * LDA];
    __shared__ __align__(16) uint32_t Bh[16 * LDB];

    int tid = threadIdx.x;
    int lane = tid & 31;
    int wid = tid >> 5;
    int wm = wid & 3;
    int wn = wid >> 2;
    int g = lane >> 2;
    int t = lane & 3;
    int r0 = blockIdx.x * 128;

    float acc[2][8][4];
#pragma unroll
    for (int i = 0; i < 2; i++)
#pragma unroll
        for (int j = 0; j < 8; j++)
#pragma unroll
            for (int k = 0; k < 4; k++) acc[i][j][k] = 0.f;

    for (int kt = 0; kt < DIN; kt += 16) {
#pragma unroll
        for (int q = 0; q < 2; q++) {
            int id = tid + q * 256;
            int row = id >> 2, c4 = id & 3;
            float4 v = make_float4(0.f, 0.f, 0.f, 0.f);
            if (r0 + row < NN)
                v = *(const float4*)(X + (size_t)(r0 + row) * DIN + kt + c4 * 4);
            *(uint4*)(Ah + row * LDA + c4 * 4) =
                make_uint4(to_tf32(v.x), to_tf32(v.y), to_tf32(v.z), to_tf32(v.w));
        }
#pragma unroll
        for (int q = 0; q < 2; q++) {
            int id = tid + q * 256;
            int kr = id >> 5, c4 = id & 31;
            float4 v = *(const float4*)(W + (size_t)(kt + kr) * DH + c4 * 4);
            *(uint4*)(Bh + kr * LDB + c4 * 4) =
                make_uint4(to_tf32(v.x), to_tf32(v.y), to_tf32(v.z), to_tf32(v.w));
        }
        __syncthreads();

#pragma unroll
        for (int kk = 0; kk < 2; kk++) {
            int kb = kk * 8;
            uint32_t ah[2][4];
#pragma unroll
            for (int mt = 0; mt < 2; mt++) {
                int rbase = (wm * 32 + mt * 16) * LDA + kb + t;
                ah[mt][0] = Ah[rbase + g * LDA];
                ah[mt][1] = Ah[rbase + (g + 8) * LDA];
                ah[mt][2] = Ah[rbase + g * LDA + 4];
                ah[mt][3] = Ah[rbase + (g + 8) * LDA + 4];
            }
            uint32_t bh[8][2];
#pragma unroll
            for (int nt = 0; nt < 8; nt++) {
                int cbase = wn * 64 + nt * 8 + g;
                bh[nt][0] = Bh[(kb + t) * LDB + cbase];
                bh[nt][1] = Bh[(kb + t + 4) * LDB + cbase];
            }
#pragma unroll
            for (int mt = 0; mt < 2; mt++)
#pragma unroll
                for (int nt = 0; nt < 8; nt++) {
                    float* d = acc[mt][nt];
                    mma_tf32(d[0], d[1], d[2], d[3],
                             ah[mt][0], ah[mt][1], ah[mt][2], ah[mt][3],
                             bh[nt][0], bh[nt][1]);
                }
        }
        __syncthreads();
    }

#pragma unroll
    for (int mt = 0; mt < 2; mt++) {
#pragma unroll
        for (int nt = 0; nt < 8; nt++) {
            int col = wn * 64 + nt * 8 + 2 * t;
            int rowa = r0 + wm * 32 + mt * 16 + g;
            int rowb = rowa + 8;
            float* d = acc[mt][nt];
            if (rowa < NN)
                *(__half2*)(g_h1h + (size_t)rowa * DH + col) = __floats2half2_rn(d[0], d[1]);
            if (rowb < NN)
                *(__half2*)(g_h1h + (size_t)rowb * DH + col) = __floats2half2_rn(d[2], d[3]);
        }
    }
}

// -------- layer1 aggregation + bias + relu -> fp16: warp per node --------
__global__ void k_agg1(const float* __restrict__ B1) {
    int t = blockIdx.x * blockDim.x + threadIdx.x;
    int w = t >> 5, lane = t & 31;
    if (w >= NN) return;
    float dv = g_dinv[w];
    float c0 = dv * dv;
    const uint2* __restrict__ Hh = (const uint2*)g_h1h;
    uint2 us = Hh[(size_t)w * 32 + lane];
    float2 s0 = __half22float2(*(__half2*)&us.x);
    float2 s1 = __half22float2(*(__half2*)&us.y);
    float4 acc = make_float4(c0 * s0.x, c0 * s0.y, c0 * s1.x, c0 * s1.y);

    int j = g_off[w];
    int end = j + g_deg[w];
    for (; j + 2 <= end; j += 2) {
        unsigned e0 = g_edge[j], e1 = g_edge[j + 1];
        int sa, sb; float ca, cb;
        unpack_edge(e0, sa, ca);
        unpack_edge(e1, sb, cb);
        uint2 u0 = Hh[(size_t)sa * 32 + lane];
        uint2 u1 = Hh[(size_t)sb * 32 + lane];
        float2 a0 = __half22float2(*(__half2*)&u0.x);
        float2 a1 = __half22float2(*(__half2*)&u0.y);
        float2 b0 = __half22float2(*(__half2*)&u1.x);
        float2 b1 = __half22float2(*(__half2*)&u1.y);
        acc.x += ca * a0.x + cb * b0.x;
        acc.y += ca * a0.y + cb * b0.y;
        acc.z += ca * a1.x + cb * b1.x;
        acc.w += ca * a1.y + cb * b1.y;
    }
    if (j < end) {
        int sa; float ca;
        unpack_edge(g_edge[j], sa, ca);
        uint2 u0 = Hh[(size_t)sa * 32 + lane];
        float2 a0 = __half22float2(*(__half2*)&u0.x);
        float2 a1 = __half22float2(*(__half2*)&u0.y);
        acc.x += ca * a0.x; acc.y += ca * a0.y;
        acc.z += ca * a1.x; acc.w += ca * a1.y;
    }
    // bias + relu, store fp16
    float4 bb = ((const float4*)B1)[lane];
    acc.x = fmaxf(acc.x + bb.x, 0.f);
    acc.y = fmaxf(acc.y + bb.y, 0.f);
    acc.z = fmaxf(acc.z + bb.z, 0.f);
    acc.w = fmaxf(acc.w + bb.w, 0.f);
    __half2 h01 = __floats2half2_rn(acc.x, acc.y);
    __half2 h23 = __floats2half2_rn(acc.z, acc.w);
    uint2 st;
    st.x = *(unsigned*)&h01;
    st.y = *(unsigned*)&h23;
    ((uint2*)g_a1h)[(size_t)w * 32 + lane] = st;
}

// -------- GEMM2: h2h[NN,40] = a1h[NN,128] @ W2[128,40] (A fp16-staged) --------
__global__ void k_gemm2(const float* __restrict__ W2) {
    __shared__ __align__(16) float As[128][65];
    __shared__ float Bs[64][40];
    int tid = threadIdx.x;
    int r0 = blockIdx.x * 128;
    int tx = tid & 7;
    int ty = tid >> 3;
    float acc[4][5];
#pragma unroll
    for (int i = 0; i < 4; i++)
#pragma unroll
        for (int c = 0; c < 5; c++) acc[i][c] = 0.f;

    for (int kt = 0; kt < DH; kt += 64) {
#pragma unroll
        for (int q = 0; q < 8; q++) {
            int id = tid + q * 256;
            int row = id >> 4, c4 = id & 15;
            float4 v = make_float4(0.f, 0.f, 0.f, 0.f);
            if (r0 + row < NN) {
                uint2 u = *(const uint2*)(g_a1h + (size_t)(r0 + row) * DH + kt + c4 * 4);
                float2 f0 = __half22float2(*(__half2*)&u.x);
                float2 f1 = __half22float2(*(__half2*)&u.y);
                v = make_float4(f0.x, f0.y, f1.x, f1.y);
            }
            As[row][c4 * 4 + 0] = v.x; As[row][c4 * 4 + 1] = v.y;
            As[row][c4 * 4 + 2] = v.z; As[row][c4 * 4 + 3] = v.w;
        }
#pragma unroll
        for (int q = 0; q < 10; q++) {
            int id = tid + q * 256;
            int k = id / 40, c = id % 40;
            Bs[k][c] = W2[(size_t)(kt + k) * DO + c];
        }
        __syncthreads();
#pragma unroll 8
        for (int k = 0; k < 64; k++) {
            float b[5];
#pragma unroll
            for (int c = 0; c < 5; c++) b[c] = Bs[k][tx * 5 + c];
#pragma unroll
            for (int i = 0; i < 4; i++) {
                float a = As[ty * 4 + i][k];
#pragma unroll
                for (int c = 0; c < 5; c++) acc[i][c] += a * b[c];
            }
        }
        __syncthreads();
    }
#pragma unroll
    for (int i = 0; i < 4; i++) {
        int row = r0 + ty * 4 + i;
        if (row < NN) {
#pragma unroll
            for (int c = 0; c < 5; c++)
                g_h2h[(size_t)row * DO + tx * 5 + c] = __float2half_rn(acc[i][c]);
        }
    }
}

// -------- layer2 aggregation + bias + log_softmax fused --------
__global__ void k_agg2_logsm(float* __restrict__ out, const float* __restrict__ B2) {
    int t = blockIdx.x * blockDim.x + threadIdx.x;
    int w = t >> 5, lane = t & 31;
    if (w >= NN) return;
    bool act = lane < 20;
    float dv = g_dinv[w];
    float c0 = dv * dv;
    const __half2* __restrict__ Hh = (const __half2*)g_h2h;
    float acc0 = 0.f, acc1 = 0.f;
    if (act) {
        float2 f = __half22float2(Hh[(size_t)w * 20 + lane]);
        acc0 = c0 * f.x;
        acc1 = c0 * f.y;
    }
    int j = g_off[w];
    int end = j + g_deg[w];
    for (; j + 2 <= end; j += 2) {
        unsigned e0 = g_edge[j], e1 = g_edge[j + 1];
        if (act) {
            int sa, sb; float ca, cb;
            unpack_edge(e0, sa, ca);
            unpack_edge(e1, sb, cb);
            float2 f0 = __half22float2(Hh[(size_t)sa * 20 + lane]);
            float2 f1 = __half22float2(Hh[(size_t)sb * 20 + lane]);
            acc0 += ca * f0.x + cb * f1.x;
            acc1 += ca * f0.y + cb * f1.y;
        }
    }
    if (j < end) {
        unsigned e0 = g_edge[j];
        if (act) {
            int sa; float ca;
            unpack_edge(e0, sa, ca);
            float2 f0 = __half22float2(Hh[(size_t)sa * 20 + lane]);
            acc0 += ca * f0.x;
            acc1 += ca * f0.y;
        }
    }
    if (act) {
        acc0 += B2[2 * lane];
        acc1 += B2[2 * lane + 1];
    }
    float m = act ? fmaxf(acc0, acc1) : __int_as_float(0xff800000);
#pragma unroll
    for (int o = 16; o > 0; o >>= 1) m = fmaxf(m, __shfl_xor_sync(0xffffffffu, m, o));
    float s = act ? (expf(acc0 - m) + expf(acc1 - m)) : 0.f;
#pragma unroll
    for (int o = 16; o > 0; o >>= 1) s += __shfl_xor_sync(0xffffffffu, s, o);
    float lse = m + logf(s);
    if (act)
        *(float2*)(out + (size_t)w * DO + 2 * lane) = make_float2(acc0 - lse, acc1 - lse);
}

// -------- launch --------
extern "C" void kernel_launch(void* const* d_in, const int* in_sizes, int n_in,
                              void* d_out, int out_size) {
    const float* x  = (const float*)d_in[0];
    const void*  ei = d_in[1];
    const float* W1 = (const float*)d_in[2];
    const float* b1 = (const float*)d_in[3];
    const float* W2 = (const float*)d_in[4];
    const float* b2 = (const float*)d_in[5];
    float* out = (float*)d_out;

    (void)in_sizes; (void)n_in; (void)out_size;

    k_init<<<(NN + 255) / 256 + 1, 256>>>((const int*)ei);          // 0
    k_deg<<<(NE + 255) / 256, 256>>>(ei);                           // 1
    k_scan_block<<<SCAN_NB, SCAN_BLK>>>();                          // 2
    k_gemm1<<<(NN + 127) / 128, 256>>>(x, W1);                      // 3  <- ncu capture slot
    k_scan_fix<<<(NN + 255) / 256, 256>>>();                        // 4
    k_scatter<<<(NE + 255) / 256, 256>>>(ei);                       // 5
    k_agg1<<<(int)(((size_t)NN * 32 + 255) / 256), 256>>>(b1);      // 6
    k_gemm2<<<(NN + 127) / 128, 256>>>(W2);                         // 7
    k_agg2_logsm<<<(int)(((size_t)NN * 32 + 255) / 256), 256>>>(out, b2);  // 8
}

// round 7
// speedup vs baseline: 1.4100x; 1.0594x over previous
#include <cuda_runtime.h>
#include <cuda_fp16.h>
#include <cstdint>

#define NN 50000
#define NE 1600000
#define DIN 256
#define DH 128
#define DO 40

#define SCAN_BLK 512
#define SCAN_NB ((NN + SCAN_BLK - 1) / SCAN_BLK)   // 98

// -------- scratch (static device globals; no allocation allowed) --------
static __device__ __align__(16) __half g_h1h[(size_t)NN * DH];   // x@W1 (fp16, gather source)
static __device__ __align__(16) __half g_a1h[(size_t)NN * DH];   // relu(agg1+b1) (fp16)
static __device__ __align__(16) __half g_h2h[(size_t)NN * DO];   // layer2 pre-agg (fp16)
static __device__ int      g_deg[NN];
static __device__ float    g_dinv[NN];
static __device__ int      g_off[NN];
static __device__ int      g_pos[NN];
static __device__ int      g_inc[SCAN_NB * SCAN_BLK];
static __device__ int      g_bsum[SCAN_NB];
static __device__ unsigned g_edge[NE];   // packed: (src << 16) | fp16(coef)
static __device__ int      g_is64;

// -------- edge index accessors (dtype-agnostic) --------
__device__ __forceinline__ int e_src(const void* ei, int t) {
    return g_is64 ? (int)((const long long*)ei)[t] : ((const int*)ei)[t];
}
__device__ __forceinline__ int e_dst(const void* ei, int t) {
    return g_is64 ? (int)((const long long*)ei)[NE + t] : ((const int*)ei)[NE + t];
}

// -------- init: zero degree counters + detect edge dtype --------
__global__ void k_init(const int* __restrict__ ei32) {
    if (blockIdx.x == gridDim.x - 1) {
        int t = threadIdx.x;
        if (t == 0) g_is64 = 1;
        __syncthreads();
        int any = 0;
        for (int i = t; i < 2048; i += blockDim.x) any |= ei32[2 * i + 1];
        if (any) g_is64 = 0;
        return;
    }
    int t = blockIdx.x * blockDim.x + threadIdx.x;
    if (t < NN) g_deg[t] = 0;
}

// -------- degree histogram: 4 edges/thread on int32 path --------
__global__ void k_deg(const void* __restrict__ ei) {
    int t = blockIdx.x * blockDim.x + threadIdx.x;
    if (!g_is64) {
        if (t < NE / 4) {
            int4 d4 = ((const int4*)((const int*)ei + NE))[t];
            if ((unsigned)d4.x < NN) atomicAdd(&g_deg[d4.x], 1);
            if ((unsigned)d4.y < NN) atomicAdd(&g_deg[d4.y], 1);
            if ((unsigned)d4.z < NN) atomicAdd(&g_deg[d4.z], 1);
            if ((unsigned)d4.w < NN) atomicAdd(&g_deg[d4.w], 1);
        }
    } else {
        for (int e = t * 4; e < t * 4 + 4 && e < NE; e++) {
            int d = (int)((const long long*)ei)[NE + e];
            if ((unsigned)d < NN) atomicAdd(&g_deg[d], 1);
        }
    }
}

// -------- scan level 1: per-block inclusive scan --------
__global__ void k_scan_block() {
    __shared__ int sh[SCAN_BLK];
    int t = threadIdx.x;
    int i = blockIdx.x * SCAN_BLK + t;
    int v = (i < NN) ? g_deg[i] : 0;
    sh[t] = v;
    __syncthreads();
#pragma unroll
    for (int o = 1; o < SCAN_BLK; o <<= 1) {
        int x = (t >= o) ? sh[t - o] : 0;
        __syncthreads();
        sh[t] += x;
        __syncthreads();
    }
    g_inc[i] = sh[t];
    if (t == SCAN_BLK - 1) g_bsum[blockIdx.x] = sh[t];
}

// -------- scan fix (+ in-block top scan) + dinv --------
__global__ void k_scan_fix() {
    __shared__ int sb[SCAN_NB];
    if (threadIdx.x == 0) {
        int run = 0;
        for (int i = 0; i < SCAN_NB; i++) { sb[i] = run; run += g_bsum[i]; }
    }
    __syncthreads();
    int t = blockIdx.x * blockDim.x + threadIdx.x;
    if (t < NN) {
        int dg = g_deg[t];
        int off = g_inc[t] - dg + sb[t / SCAN_BLK];  // exclusive
        g_off[t] = off;
        g_pos[t] = off;
        g_dinv[t] = rsqrtf((float)(dg + 1));
    }
}

// -------- CSR fill: packed (src:16 | coef:fp16) --------
__global__ void k_scatter(const void* __restrict__ ei) {
    int t = blockIdx.x * blockDim.x + threadIdx.x;
    if (t < NE) {
        int s = e_src(ei, t);
        int d = e_dst(ei, t);
        if ((unsigned)s < NN && (unsigned)d < NN) {
            int slot = atomicAdd(&g_pos[d], 1);
            unsigned hb = __half_as_ushort(__float2half_rn(g_dinv[s] * g_dinv[d]));
            g_edge[slot] = ((unsigned)s << 16) | hb;
        }
    }
}

__device__ __forceinline__ void unpack_edge(unsigned e, int& s, float& c) {
    s = (int)(e >> 16);
    c = __half2float(__ushort_as_half((unsigned short)(e & 0xffffu)));
}

// -------- async copy helpers --------
__device__ __forceinline__ void cp_async16(void* smem, const void* gmem, bool pred) {
    uint32_t sa = (uint32_t)__cvta_generic_to_shared(smem);
    int sz = pred ? 16 : 0;
    asm volatile("cp.async.cg.shared.global [%0], [%1], 16, %2;" :: "r"(sa), "l"(gmem), "r"(sz));
}
__device__ __forceinline__ void cp_commit() { asm volatile("cp.async.commit_group;"); }
template <int N>
__device__ __forceinline__ void cp_wait() { asm volatile("cp.async.wait_group %0;" :: "n"(N)); }

__device__ __forceinline__ void mma_tf32(float& d0, float& d1, float& d2, float& d3,
                                         uint32_t a0, uint32_t a1, uint32_t a2, uint32_t a3,
                                         uint32_t b0, uint32_t b1) {
    asm volatile(
        "mma.sync.aligned.m16n8k8.row.col.f32.tf32.tf32.f32 "
        "{%0,%1,%2,%3}, {%4,%5,%6,%7}, {%8,%9}, {%0,%1,%2,%3};"
        : "+f"(d0), "+f"(d1), "+f"(d2), "+f"(d3)
        : "r"(a0), "r"(a1), "r"(a2), "r"(a3), "r"(b0), "r"(b1));
}

// -------- GEMM1 (tf32 on raw fp32 bits, cp.async double-buffered) --------
// h1h[NN,128] = X[NN,256] @ W[256,128]; BM=128, BN=128, BK=16, 256 threads.
#define LDA 20
#define LDB 136
#define NT (DIN / 16)   // 16 k-tiles
__global__ void __launch_bounds__(256)
k_gemm1(const float* __restrict__ X, const float* __restrict__ W) {
    __shared__ __align__(16) uint32_t Ah[2][128 * LDA];
    __shared__ __align__(16) uint32_t Bh[2][16 * LDB];

    int tid = threadIdx.x;
    int lane = tid & 31;
    int wid = tid >> 5;
    int wm = wid & 3;
    int wn = wid >> 2;
    int g = lane >> 2;
    int t = lane & 3;
    int r0 = blockIdx.x * 128;

    // per-thread staging coords
    int arow = tid >> 2, ac4 = tid & 3;          // +q*64 rows via id offset
    int brow = tid >> 5, bc4 = tid & 31;         // +q*8 rows

    auto load_tile = [&](int it, int buf) {
#pragma unroll
        for (int q = 0; q < 2; q++) {
            int row = arow + q * 64;
            cp_async16(&Ah[buf][row * LDA + ac4 * 4],
                       X + (size_t)(r0 + row) * DIN + it * 16 + ac4 * 4,
                       r0 + row < NN);
        }
#pragma unroll
        for (int q = 0; q < 2; q++) {
            int kr = brow + q * 8;
            cp_async16(&Bh[buf][kr * LDB + bc4 * 4],
                       W + (size_t)(it * 16 + kr) * DH + bc4 * 4, true);
        }
    };

    float acc[2][8][4];
#pragma unroll
    for (int i = 0; i < 2; i++)
#pragma unroll
        for (int j = 0; j < 8; j++)
#pragma unroll
            for (int k = 0; k < 4; k++) acc[i][j][k] = 0.f;

    load_tile(0, 0);
    cp_commit();

    for (int it = 0; it < NT; it++) {
        int buf = it & 1;
        if (it + 1 < NT) {
            load_tile(it + 1, (it + 1) & 1);
            cp_commit();
            cp_wait<1>();
        } else {
            cp_wait<0>();
        }
        __syncthreads();

#pragma unroll
        for (int kk = 0; kk < 2; kk++) {
            int kb = kk * 8;
            uint32_t ah[2][4];
#pragma unroll
            for (int mt = 0; mt < 2; mt++) {
                int rbase = (wm * 32 + mt * 16) * LDA + kb + t;
                ah[mt][0] = Ah[buf][rbase + g * LDA];
                ah[mt][1] = Ah[buf][rbase + (g + 8) * LDA];
                ah[mt][2] = Ah[buf][rbase + g * LDA + 4];
                ah[mt][3] = Ah[buf][rbase + (g + 8) * LDA + 4];
            }
            uint32_t bh[8][2];
#pragma unroll
            for (int nt = 0; nt < 8; nt++) {
                int cbase = wn * 64 + nt * 8 + g;
                bh[nt][0] = Bh[buf][(kb + t) * LDB + cbase];
                bh[nt][1] = Bh[buf][(kb + t + 4) * LDB + cbase];
            }
#pragma unroll
            for (int mt = 0; mt < 2; mt++)
#pragma unroll
                for (int nt = 0; nt < 8; nt++) {
                    float* d = acc[mt][nt];
                    mma_tf32(d[0], d[1], d[2], d[3],
                             ah[mt][0], ah[mt][1], ah[mt][2], ah[mt][3],
                             bh[nt][0], bh[nt][1]);
                }
        }
        __syncthreads();
    }

#pragma unroll
    for (int mt = 0; mt < 2; mt++) {
#pragma unroll
        for (int nt = 0; nt < 8; nt++) {
            int col = wn * 64 + nt * 8 + 2 * t;
            int rowa = r0 + wm * 32 + mt * 16 + g;
            int rowb = rowa + 8;
            float* d = acc[mt][nt];
            if (rowa < NN)
                *(__half2*)(g_h1h + (size_t)rowa * DH + col) = __floats2half2_rn(d[0], d[1]);
            if (rowb < NN)
                *(__half2*)(g_h1h + (size_t)rowb * DH + col) = __floats2half2_rn(d[2], d[3]);
        }
    }
}

// -------- layer1 aggregation + bias + relu -> fp16: warp per node --------
__global__ void k_agg1(const float* __restrict__ B1) {
    int t = blockIdx.x * blockDim.x + threadIdx.x;
    int w = t >> 5, lane = t & 31;
    if (w >= NN) return;
    float dv = g_dinv[w];
    float c0 = dv * dv;
    const uint2* __restrict__ Hh = (const uint2*)g_h1h;
    uint2 us = Hh[(size_t)w * 32 + lane];
    float2 s0 = __half22float2(*(__half2*)&us.x);
    float2 s1 = __half22float2(*(__half2*)&us.y);
    float4 acc = make_float4(c0 * s0.x, c0 * s0.y, c0 * s1.x, c0 * s1.y);

    int j = g_off[w];
    int end = j + g_deg[w];
    for (; j + 2 <= end; j += 2) {
        unsigned e0 = g_edge[j], e1 = g_edge[j + 1];
        int sa, sb; float ca, cb;
        unpack_edge(e0, sa, ca);
        unpack_edge(e1, sb, cb);
        uint2 u0 = Hh[(size_t)sa * 32 + lane];
        uint2 u1 = Hh[(size_t)sb * 32 + lane];
        float2 a0 = __half22float2(*(__half2*)&u0.x);
        float2 a1 = __half22float2(*(__half2*)&u0.y);
        float2 b0 = __half22float2(*(__half2*)&u1.x);
        float2 b1 = __half22float2(*(__half2*)&u1.y);
        acc.x += ca * a0.x + cb * b0.x;
        acc.y += ca * a0.y + cb * b0.y;
        acc.z += ca * a1.x + cb * b1.x;
        acc.w += ca * a1.y + cb * b1.y;
    }
    if (j < end) {
        int sa; float ca;
        unpack_edge(g_edge[j], sa, ca);
        uint2 u0 = Hh[(size_t)sa * 32 + lane];
        float2 a0 = __half22float2(*(__half2*)&u0.x);
        float2 a1 = __half22float2(*(__half2*)&u0.y);
        acc.x += ca * a0.x; acc.y += ca * a0.y;
        acc.z += ca * a1.x; acc.w += ca * a1.y;
    }
    float4 bb = ((const float4*)B1)[lane];
    acc.x = fmaxf(acc.x + bb.x, 0.f);
    acc.y = fmaxf(acc.y + bb.y, 0.f);
    acc.z = fmaxf(acc.z + bb.z, 0.f);
    acc.w = fmaxf(acc.w + bb.w, 0.f);
    __half2 h01 = __floats2half2_rn(acc.x, acc.y);
    __half2 h23 = __floats2half2_rn(acc.z, acc.w);
    uint2 st;
    st.x = *(unsigned*)&h01;
    st.y = *(unsigned*)&h23;
    ((uint2*)g_a1h)[(size_t)w * 32 + lane] = st;
}

// -------- GEMM2: h2h[NN,40] = a1h[NN,128] @ W2[128,40] --------
__global__ void k_gemm2(const float* __restrict__ W2) {
    __shared__ __align__(16) float As[128][65];
    __shared__ float Bs[64][40];
    int tid = threadIdx.x;
    int r0 = blockIdx.x * 128;
    int tx = tid & 7;
    int ty = tid >> 3;
    float acc[4][5];
#pragma unroll
    for (int i = 0; i < 4; i++)
#pragma unroll
        for (int c = 0; c < 5; c++) acc[i][c] = 0.f;

    for (int kt = 0; kt < DH; kt += 64) {
#pragma unroll
        for (int q = 0; q < 8; q++) {
            int id = tid + q * 256;
            int row = id >> 4, c4 = id & 15;
            float4 v = make_float4(0.f, 0.f, 0.f, 0.f);
            if (r0 + row < NN) {
                uint2 u = *(const uint2*)(g_a1h + (size_t)(r0 + row) * DH + kt + c4 * 4);
                float2 f0 = __half22float2(*(__half2*)&u.x);
                float2 f1 = __half22float2(*(__half2*)&u.y);
                v = make_float4(f0.x, f0.y, f1.x, f1.y);
            }
            As[row][c4 * 4 + 0] = v.x; As[row][c4 * 4 + 1] = v.y;
            As[row][c4 * 4 + 2] = v.z; As[row][c4 * 4 + 3] = v.w;
        }
#pragma unroll
        for (int q = 0; q < 10; q++) {
            int id = tid + q * 256;
            int k = id / 40, c = id % 40;
            Bs[k][c] = W2[(size_t)(kt + k) * DO + c];
        }
        __syncthreads();
#pragma unroll 8
        for (int k = 0; k < 64; k++) {
            float b[5];
#pragma unroll
            for (int c = 0; c < 5; c++) b[c] = Bs[k][tx * 5 + c];
#pragma unroll
            for (int i = 0; i < 4; i++) {
                float a = As[ty * 4 + i][k];
#pragma unroll
                for (int c = 0; c < 5; c++) acc[i][c] += a * b[c];
            }
        }
        __syncthreads();
    }
#pragma unroll
    for (int i = 0; i < 4; i++) {
        int row = r0 + ty * 4 + i;
        if (row < NN) {
#pragma unroll
            for (int c = 0; c < 5; c++)
                g_h2h[(size_t)row * DO + tx * 5 + c] = __float2half_rn(acc[i][c]);
        }
    }
}

// -------- layer2 aggregation + bias + log_softmax fused --------
__global__ void k_agg2_logsm(float* __restrict__ out, const float* __restrict__ B2) {
    int t = blockIdx.x * blockDim.x + threadIdx.x;
    int w = t >> 5, lane = t & 31;
    if (w >= NN) return;
    bool act = lane < 20;
    float dv = g_dinv[w];
    float c0 = dv * dv;
    const __half2* __restrict__ Hh = (const __half2*)g_h2h;
    float acc0 = 0.f, acc1 = 0.f;
    if (act) {
        float2 f = __half22float2(Hh[(size_t)w * 20 + lane]);
        acc0 = c0 * f.x;
        acc1 = c0 * f.y;
    }
    int j = g_off[w];
    int end = j + g_deg[w];
    for (; j + 2 <= end; j += 2) {
        unsigned e0 = g_edge[j], e1 = g_edge[j + 1];
        if (act) {
            int sa, sb; float ca, cb;
            unpack_edge(e0, sa, ca);
            unpack_edge(e1, sb, cb);
            float2 f0 = __half22float2(Hh[(size_t)sa * 20 + lane]);
            float2 f1 = __half22float2(Hh[(size_t)sb * 20 + lane]);
            acc0 += ca * f0.x + cb * f1.x;
            acc1 += ca * f0.y + cb * f1.y;
        }
    }
    if (j < end) {
        unsigned e0 = g_edge[j];
        if (act) {
            int sa; float ca;
            unpack_edge(e0, sa, ca);
            float2 f0 = __half22float2(Hh[(size_t)sa * 20 + lane]);
            acc0 += ca * f0.x;
            acc1 += ca * f0.y;
        }
    }
    if (act) {
        acc0 += B2[2 * lane];
        acc1 += B2[2 * lane + 1];
    }
    float m = act ? fmaxf(acc0, acc1) : __int_as_float(0xff800000);
#pragma unroll
    for (int o = 16; o > 0; o >>= 1) m = fmaxf(m, __shfl_xor_sync(0xffffffffu, m, o));
    float s = act ? (expf(acc0 - m) + expf(acc1 - m)) : 0.f;
#pragma unroll
    for (int o = 16; o > 0; o >>= 1) s += __shfl_xor_sync(0xffffffffu, s, o);
    float lse = m + logf(s);
    if (act)
        *(float2*)(out + (size_t)w * DO + 2 * lane) = make_float2(acc0 - lse, acc1 - lse);
}

// -------- launch --------
extern "C" void kernel_launch(void* const* d_in, const int* in_sizes, int n_in,
                              void* d_out, int out_size) {
    const float* x  = (const float*)d_in[0];
    const void*  ei = d_in[1];
    const float* W1 = (const float*)d_in[2];
    const float* b1 = (const float*)d_in[3];
    const float* W2 = (const float*)d_in[4];
    const float* b2 = (const float*)d_in[5];
    float* out = (float*)d_out;

    (void)in_sizes; (void)n_in; (void)out_size;

    k_init<<<(NN + 255) / 256 + 1, 256>>>((const int*)ei);          // 0
    k_deg<<<(NE / 4 + 255) / 256, 256>>>(ei);                       // 1
    k_scan_block<<<SCAN_NB, SCAN_BLK>>>();                          // 2
    k_gemm1<<<(NN + 127) / 128, 256>>>(x, W1);                      // 3  <- ncu capture slot
    k_scan_fix<<<(NN + 255) / 256, 256>>>();                        // 4
    k_scatter<<<(NE + 255) / 256, 256>>>(ei);                       // 5
    k_agg1<<<(int)(((size_t)NN * 32 + 255) / 256), 256>>>(b1);      // 6
    k_gemm2<<<(NN + 127) / 128, 256>>>(W2);                         // 7
    k_agg2_logsm<<<(int)(((size_t)NN * 32 + 255) / 256), 256>>>(out, b2);  // 8
}